// round 7
// baseline (speedup 1.0000x reference)
#include <cuda_runtime.h>
#include <cuda_fp16.h>
#include <math.h>
#include <stdint.h>

// Problem constants: N rows up to 100000, MUL=128, x row = 512 floats.
#define MAXN 100000
#define SQ2F 1.41421356237309515f

// Scratch (allocation-free rule: __device__ globals). fp16 for GEMM-facing data.
__device__ __half g_scal [(size_t)MAXN * 384];
__device__ __half g_h    [(size_t)MAXN * 384];
__device__ __half g_vg   [(size_t)MAXN * 256 * 3];
__device__ float  g_outs [(size_t)MAXN * 128];
__device__ float  g_outv [(size_t)MAXN * 128 * 3];
// Packed (transposed to [N,K] K-major, fp16) weights.
__device__ __half g_w1p[384 * 384];
__device__ __half g_w2p[640 * 384];
__device__ __half g_wsp[128 * 384];
__device__ __half g_wvp[128 * 256];

__device__ __forceinline__ float silu_f(float v) { return v / (1.0f + expf(-v)); }

__device__ __forceinline__ uint32_t smem_u32(const void* p) {
    uint32_t a;
    asm("{ .reg .u64 t; cvta.to.shared.u64 t, %1; cvt.u32.u64 %0, t; }" : "=r"(a) : "l"(p));
    return a;
}

__device__ __forceinline__ void cp16(uint32_t dst, const void* src, int sz) {
    asm volatile("cp.async.cg.shared.global [%0], [%1], 16, %2;"
                 :: "r"(dst), "l"(src), "r"(sz) : "memory");
}

__device__ __forceinline__ void ldsm_x4(uint32_t addr, unsigned& r0, unsigned& r1,
                                        unsigned& r2, unsigned& r3) {
    asm volatile("ldmatrix.sync.aligned.m8n8.x4.shared.b16 {%0,%1,%2,%3}, [%4];"
                 : "=r"(r0), "=r"(r1), "=r"(r2), "=r"(r3) : "r"(addr));
}

// ---------------------------------------------------------------------------
// Weight pack: Wp[n*K + k] = fp16(W[k*ldw + n]); keep first Ncols columns.
// ---------------------------------------------------------------------------
__global__ void pack_w_kernel(const float* __restrict__ W, __half* __restrict__ Wp,
                              int K, int Ncols, int ldw) {
    int idx = blockIdx.x * blockDim.x + threadIdx.x;
    if (idx >= Ncols * K) return;
    int n = idx / K;
    int k = idx - n * K;
    Wp[idx] = __float2half(W[(size_t)k * ldw + n]);
}

// ---------------------------------------------------------------------------
// K1: scal[n,384] = [s, s*s, |v|^2] in fp16.
// ---------------------------------------------------------------------------
__global__ void prep_scal_kernel(const float* __restrict__ x, __half* __restrict__ scal, int n) {
    int idx = blockIdx.x * blockDim.x + threadIdx.x;
    if (idx >= n * 128) return;
    int row = idx >> 7;
    int u = idx & 127;
    const float* xr = x + (size_t)row * 512;
    float s  = xr[u];
    float v0 = xr[128 + u * 3 + 0];
    float v1 = xr[128 + u * 3 + 1];
    float v2 = xr[128 + u * 3 + 2];
    __half* sr = scal + (size_t)row * 384;
    sr[u]       = __float2half(s);
    sr[128 + u] = __float2half(s * s);
    sr[256 + u] = __float2half(v0 * v0 + v1 * v1 + v2 * v2);
}

// ---------------------------------------------------------------------------
// FP16 mma.sync GEMM (fp32 acc), pipelined, ldmatrix fragment loads.
//   C[M, ncols*128] = A[M,K] @ Bp^T, Bp packed [N,K] row-major.
// Block 128x128, BK=32, 3-stage cp.async, 4 warps (2x2 of 64x64 warp tiles).
// MODE: 0 = plain float store, 1 = silu fp16 store, 2 = gate-fuse epilogue
// (no C store; applies gates to scal in place and builds vg planes from x).
// ---------------------------------------------------------------------------
#define TILE_HALVES 5120            // 128*40 (stride 40 halves = 20 words, pad 8)
#define STAGE_HALVES 10240          // A tile + B tile

template <int MODE, typename OT>
__global__ __launch_bounds__(128) void gemm_fp16_kernel(
    const __half* __restrict__ A, int lda, long long bsA,
    const __half* __restrict__ Bp,
    OT* __restrict__ C, int ldc, long long bsC,
    int M, int K,
    __half* __restrict__ scal, __half* __restrict__ vg,
    const float* __restrict__ x, int nrows)
{
    extern __shared__ __half smh[];
    const uint32_t sb = smem_u32(smh);

    A += (size_t)blockIdx.z * bsA;
    C += (size_t)blockIdx.z * bsC;

    const int tid  = threadIdx.x;
    const int w    = tid >> 5;
    const int lane = tid & 31;
    const int g    = lane >> 2;       // 0..7
    const int tg   = lane & 3;        // 0..3
    const int wm   = (w & 1) * 64;
    const int wn   = (w >> 1) * 64;
    const int rowBase = blockIdx.y * 128;
    const int colBase = blockIdx.x * 128;
    const int T = K >> 5;             // BK=32 steps

    // ldmatrix lane roles: quadrant q covers (row +8 if q&1, k-half +8 if q>>1).
    const int l8   = lane & 7;
    const int q    = lane >> 3;
    const int rsel = l8 + (q & 1) * 8;       // row within 16-row block
    const int wsel = (q >> 1) * 4;           // word offset for k8-half

    auto load_stage = [&](int s, int kt) {
        const int k0 = kt << 5;
        const uint32_t ab = sb + (uint32_t)(s * STAGE_HALVES) * 2u;
        const uint32_t bb = ab + TILE_HALVES * 2u;
#pragma unroll
        for (int i = 0; i < 4; i++) {
            int flat = i * 128 + tid;        // 0..511
            int r = flat >> 2;               // 0..127
            int c = flat & 3;                // chunk of 8 halves (16B)
            uint32_t so = (uint32_t)(r * 40 + c * 8) * 2u;
            int gr = rowBase + r;
            const __half* srcA = A + (size_t)(gr < M ? gr : 0) * lda + k0 + c * 8;
            cp16(ab + so, srcA, gr < M ? 16 : 0);
            const __half* srcB = Bp + (size_t)(colBase + r) * K + k0 + c * 8;
            cp16(bb + so, srcB, 16);
        }
        asm volatile("cp.async.commit_group;" ::: "memory");
    };

    float acc[4][8][4];
#pragma unroll
    for (int mt = 0; mt < 4; mt++)
#pragma unroll
        for (int nt = 0; nt < 8; nt++)
#pragma unroll
            for (int i = 0; i < 4; i++) acc[mt][nt][i] = 0.0f;

    load_stage(0, 0);
    load_stage(1, 1);

    for (int kt = 0; kt < T; kt++) {
        const int s = kt % 3;
        if (kt + 1 < T) asm volatile("cp.async.wait_group 1;" ::: "memory");
        else            asm volatile("cp.async.wait_group 0;" ::: "memory");
        __syncthreads();
        if (kt + 2 < T) load_stage((kt + 2) % 3, kt + 2);

        const uint32_t a_base = sb + (uint32_t)(s * STAGE_HALVES) * 2u;
        const uint32_t b_base = a_base + TILE_HALVES * 2u;
#pragma unroll
        for (int kf = 0; kf < 2; kf++) {
            const int kw = kf * 8 + wsel;    // word offset in row
            unsigned a[4][4], b[8][2];
#pragma unroll
            for (int mt = 0; mt < 4; mt++) {
                uint32_t addr = a_base + (uint32_t)((wm + mt * 16 + rsel) * 20 + kw) * 4u;
                ldsm_x4(addr, a[mt][0], a[mt][1], a[mt][2], a[mt][3]);
            }
#pragma unroll
            for (int p = 0; p < 4; p++) {
                uint32_t addr = b_base + (uint32_t)((wn + p * 16 + rsel) * 20 + kw) * 4u;
                ldsm_x4(addr, b[2 * p][0], b[2 * p + 1][0], b[2 * p][1], b[2 * p + 1][1]);
            }
#pragma unroll
            for (int mt = 0; mt < 4; mt++)
#pragma unroll
                for (int nt = 0; nt < 8; nt++) {
                    asm volatile(
                        "mma.sync.aligned.m16n8k16.row.col.f32.f16.f16.f32 "
                        "{%0,%1,%2,%3}, {%4,%5,%6,%7}, {%8,%9}, {%0,%1,%2,%3};\n"
                        : "+f"(acc[mt][nt][0]), "+f"(acc[mt][nt][1]),
                          "+f"(acc[mt][nt][2]), "+f"(acc[mt][nt][3])
                        : "r"(a[mt][0]), "r"(a[mt][1]), "r"(a[mt][2]), "r"(a[mt][3]),
                          "r"(b[nt][0]), "r"(b[nt][1]));
                }
        }
        __syncthreads();
    }

    // ---- Epilogue ----
    if (MODE == 2) {
        // Gate-fuse: g = silu(acc). Segment decided by colBase (whole CTA).
        auto apply = [&](int row, int col, float g0, float g1) {
            if (row >= M) return;
            g0 = silu_f(g0); g1 = silu_f(g1);
            if (colBase < 384) {
                __half2* p = reinterpret_cast<__half2*>(scal + (size_t)row * 384 + col);
                float2 old = __half22float2(*p);
                *p = __floats2half2_rn(old.x * g0, old.y * g1);
            } else if (colBase < 512) {
                int u = col - 384;
                const float* xr = x + (size_t)row * 512;
#pragma unroll
                for (int i = 0; i < 3; i++) {
                    float v0 = xr[128 + u * 3 + i];
                    float v1 = xr[128 + (u + 1) * 3 + i];
                    __half2* p = reinterpret_cast<__half2*>(
                        vg + ((size_t)i * nrows + row) * 256 + u);
                    *p = __floats2half2_rn(v0 * g0, v1 * g1);
                }
            } else {
                int u = col - 512;
                const float* xr = x + (size_t)row * 512;
                float c0 = SQ2F * xr[u] * g0;
                float c1 = SQ2F * xr[u + 1] * g1;
#pragma unroll
                for (int i = 0; i < 3; i++) {
                    float v0 = xr[128 + u * 3 + i];
                    float v1 = xr[128 + (u + 1) * 3 + i];
                    __half2* p = reinterpret_cast<__half2*>(
                        vg + ((size_t)i * nrows + row) * 256 + 128 + u);
                    *p = __floats2half2_rn(v0 * c0, v1 * c1);
                }
            }
        };
#pragma unroll
        for (int mt = 0; mt < 4; mt++) {
            int r0 = rowBase + wm + mt * 16 + g;
#pragma unroll
            for (int nt = 0; nt < 8; nt++) {
                int c0 = colBase + wn + nt * 8 + 2 * tg;
                apply(r0,     c0, acc[mt][nt][0], acc[mt][nt][1]);
                apply(r0 + 8, c0, acc[mt][nt][2], acc[mt][nt][3]);
            }
        }
    } else {
#pragma unroll
        for (int mt = 0; mt < 4; mt++) {
            int r0 = rowBase + wm + mt * 16 + g;
#pragma unroll
            for (int nt = 0; nt < 8; nt++) {
                int c0 = colBase + wn + nt * 8 + 2 * tg;
                float2 lo = make_float2(acc[mt][nt][0], acc[mt][nt][1]);
                float2 hi = make_float2(acc[mt][nt][2], acc[mt][nt][3]);
                if (MODE == 1) {
                    lo.x = silu_f(lo.x); lo.y = silu_f(lo.y);
                    hi.x = silu_f(hi.x); hi.y = silu_f(hi.y);
                }
                if (r0 < M) {
                    OT* cr = C + (size_t)r0 * ldc + c0;
                    if (sizeof(OT) == 2) *reinterpret_cast<__half2*>(cr) = __float22half2_rn(lo);
                    else                 *reinterpret_cast<float2*>(cr) = lo;
                }
                if (r0 + 8 < M) {
                    OT* cr = C + (size_t)(r0 + 8) * ldc + c0;
                    if (sizeof(OT) == 2) *reinterpret_cast<__half2*>(cr) = __float22half2_rn(hi);
                    else                 *reinterpret_cast<float2*>(cr) = hi;
                }
            }
        }
    }
}

// ---------------------------------------------------------------------------
// K7: residuals + scalar layernorm + vector RMS norm, write output [n,512].
// ---------------------------------------------------------------------------
__global__ void finalize_kernel(const float* __restrict__ x, const float* __restrict__ outs,
                                const float* __restrict__ outv, float* __restrict__ out, int n) {
    int gw = (int)((blockIdx.x * blockDim.x + threadIdx.x) >> 5);
    int lane = threadIdx.x & 31;
    if (gw >= n) return;
    const float* xr = x + (size_t)gw * 512;
    float* orow = out + (size_t)gw * 512;

    float so[4];
    float sum = 0.f;
#pragma unroll
    for (int t = 0; t < 4; t++) {
        int u = lane + 32 * t;
        so[t] = outs[(size_t)gw * 128 + u] + xr[u];
        sum += so[t];
    }
#pragma unroll
    for (int o = 16; o > 0; o >>= 1) sum += __shfl_xor_sync(0xffffffffu, sum, o);
    float mean = sum * (1.0f / 128.0f);
    float ssum = 0.f;
#pragma unroll
    for (int t = 0; t < 4; t++) {
        so[t] -= mean;
        ssum += so[t] * so[t];
    }
#pragma unroll
    for (int o = 16; o > 0; o >>= 1) ssum += __shfl_xor_sync(0xffffffffu, ssum, o);
    float inv = 1.0f / (sqrtf(ssum * (1.0f / 128.0f)) + 1e-6f);
#pragma unroll
    for (int t = 0; t < 4; t++) orow[lane + 32 * t] = so[t] * inv;

    float vo[4][3];
    float vs = 0.f;
#pragma unroll
    for (int t = 0; t < 4; t++) {
        int u = lane + 32 * t;
#pragma unroll
        for (int i = 0; i < 3; i++) {
            vo[t][i] = outv[((size_t)i * n + gw) * 128 + u] + xr[128 + u * 3 + i];
            vs += vo[t][i] * vo[t][i];
        }
    }
#pragma unroll
    for (int o = 16; o > 0; o >>= 1) vs += __shfl_xor_sync(0xffffffffu, vs, o);
    float vinv = 1.0f / (sqrtf(vs * (1.0f / 128.0f)) + 1e-6f);
#pragma unroll
    for (int t = 0; t < 4; t++) {
        int u = lane + 32 * t;
#pragma unroll
        for (int i = 0; i < 3; i++)
            orow[128 + u * 3 + i] = vo[t][i] * vinv;
    }
}

// ---------------------------------------------------------------------------
extern "C" void kernel_launch(void* const* d_in, const int* in_sizes, int n_in,
                              void* d_out, int out_size) {
    const float* x  = (const float*)d_in[0];
    const float* W1 = (const float*)d_in[1];   // [384,384]
    const float* W2 = (const float*)d_in[2];   // [384,768] (cols 640:768 dead)
    const float* Ws = (const float*)d_in[3];   // [384,128]
    const float* Wv = (const float*)d_in[4];   // [256,128]
    float* out = (float*)d_out;
    int n = in_sizes[0] / 512;

    __half *scal, *h, *vg, *w1p, *w2p, *wsp, *wvp;
    float *outs, *outv;
    cudaGetSymbolAddress((void**)&scal,  g_scal);
    cudaGetSymbolAddress((void**)&h,     g_h);
    cudaGetSymbolAddress((void**)&vg,    g_vg);
    cudaGetSymbolAddress((void**)&outs,  g_outs);
    cudaGetSymbolAddress((void**)&outv,  g_outv);
    cudaGetSymbolAddress((void**)&w1p,   g_w1p);
    cudaGetSymbolAddress((void**)&w2p,   g_w2p);
    cudaGetSymbolAddress((void**)&wsp,   g_wsp);
    cudaGetSymbolAddress((void**)&wvp,   g_wvp);

    const int SMEM_BYTES = 3 * STAGE_HALVES * 2;   // 61440
    cudaFuncSetAttribute((const void*)gemm_fp16_kernel<1, __half>,
                         cudaFuncAttributeMaxDynamicSharedMemorySize, SMEM_BYTES);
    cudaFuncSetAttribute((const void*)gemm_fp16_kernel<2, __half>,
                         cudaFuncAttributeMaxDynamicSharedMemorySize, SMEM_BYTES);
    cudaFuncSetAttribute((const void*)gemm_fp16_kernel<0, float>,
                         cudaFuncAttributeMaxDynamicSharedMemorySize, SMEM_BYTES);

    int mblocks = (n + 127) / 128;

    // Pack weights -> [N,K] K-major fp16.
    pack_w_kernel<<<(384 * 384 + 255) / 256, 256>>>(W1, w1p, 384, 384, 384);
    pack_w_kernel<<<(640 * 384 + 255) / 256, 256>>>(W2, w2p, 384, 640, 768);
    pack_w_kernel<<<(128 * 384 + 255) / 256, 256>>>(Ws, wsp, 384, 128, 128);
    pack_w_kernel<<<(128 * 256 + 255) / 256, 256>>>(Wv, wvp, 256, 128, 128);

    // K1: scal features (fp16)
    prep_scal_kernel<<<(n * 128 + 255) / 256, 256>>>(x, scal, n);

    // G1: h = silu(scal @ W1) -> fp16
    dim3 g1(3, mblocks, 1);
    gemm_fp16_kernel<1, __half><<<g1, 128, SMEM_BYTES>>>(
        scal, 384, 0LL, w1p, h, 384, 0LL, n, 384, nullptr, nullptr, nullptr, n);

    // G2+gate fusion: gates = silu(h @ W2[:, :640]) applied directly:
    //   cols 0-383 -> scal *= g ; 384-511 -> vg[u] = v*g ; 512-639 -> vg[128+u] = sqrt2*s*v*g
    dim3 g2(5, mblocks, 1);
    gemm_fp16_kernel<2, __half><<<g2, 128, SMEM_BYTES>>>(
        h, 384, 0LL, w2p, h /*unused*/, 640, 0LL, n, 384, scal, vg, x, n);

    // G5: outs = scal_gated @ Ws -> fp32
    dim3 g5(1, mblocks, 1);
    gemm_fp16_kernel<0, float><<<g5, 128, SMEM_BYTES>>>(
        scal, 384, 0LL, wsp, outs, 128, 0LL, n, 384, nullptr, nullptr, nullptr, n);

    // G6: outv_i = vg_i @ Wv (3 planes over z) -> fp32
    dim3 g6(1, mblocks, 3);
    gemm_fp16_kernel<0, float><<<g6, 128, SMEM_BYTES>>>(
        vg, 256, (long long)n * 256, wvp, outv, 128, (long long)n * 128, n, 256,
        nullptr, nullptr, nullptr, n);

    // K7: residual + norms + output
    finalize_kernel<<<(n + 7) / 8, 256>>>(x, outs, outv, out, n);
}

// round 8
// speedup vs baseline: 1.2047x; 1.2047x over previous
#include <cuda_runtime.h>
#include <cuda_fp16.h>
#include <math.h>
#include <stdint.h>

// Problem constants: N rows up to 100000, MUL=128, x row = 512 floats.
#define MAXN 100000
#define SQ2F 1.41421356237309515f

// Scratch (allocation-free rule: __device__ globals). fp16 for GEMM-facing data.
__device__ __half g_scal [(size_t)MAXN * 384];
__device__ __half g_h    [(size_t)MAXN * 384];
__device__ __half g_gates[(size_t)MAXN * 640];
__device__ __half g_vg   [(size_t)MAXN * 256 * 3];
__device__ float  g_outs [(size_t)MAXN * 128];
__device__ float  g_outv [(size_t)MAXN * 128 * 3];
// Packed (transposed to [N,K] K-major, fp16) weights.
__device__ __half g_w1p[384 * 384];
__device__ __half g_w2p[640 * 384];
__device__ __half g_wsp[128 * 384];
__device__ __half g_wvp[128 * 256];

__device__ __forceinline__ float silu_f(float v) { return v / (1.0f + expf(-v)); }

__device__ __forceinline__ uint32_t smem_u32(const void* p) {
    uint32_t a;
    asm("{ .reg .u64 t; cvta.to.shared.u64 t, %1; cvt.u32.u64 %0, t; }" : "=r"(a) : "l"(p));
    return a;
}

__device__ __forceinline__ void cp16(uint32_t dst, const void* src, int sz) {
    asm volatile("cp.async.cg.shared.global [%0], [%1], 16, %2;"
                 :: "r"(dst), "l"(src), "r"(sz) : "memory");
}

__device__ __forceinline__ void ldsm_x4(uint32_t addr, unsigned& r0, unsigned& r1,
                                        unsigned& r2, unsigned& r3) {
    asm volatile("ldmatrix.sync.aligned.m8n8.x4.shared.b16 {%0,%1,%2,%3}, [%4];"
                 : "=r"(r0), "=r"(r1), "=r"(r2), "=r"(r3) : "r"(addr));
}

// ---------------------------------------------------------------------------
// Weight pack: Wp[n*K + k] = fp16(W[k*ldw + n]); keep first Ncols columns.
// ---------------------------------------------------------------------------
__global__ void pack_w_kernel(const float* __restrict__ W, __half* __restrict__ Wp,
                              int K, int Ncols, int ldw) {
    int idx = blockIdx.x * blockDim.x + threadIdx.x;
    if (idx >= Ncols * K) return;
    int n = idx / K;
    int k = idx - n * K;
    Wp[idx] = __float2half(W[(size_t)k * ldw + n]);
}

// ---------------------------------------------------------------------------
// K1: scal[n,384] = [s, s*s, |v|^2] in fp16.
// ---------------------------------------------------------------------------
__global__ void prep_scal_kernel(const float* __restrict__ x, __half* __restrict__ scal, int n) {
    int idx = blockIdx.x * blockDim.x + threadIdx.x;
    if (idx >= n * 128) return;
    int row = idx >> 7;
    int u = idx & 127;
    const float* xr = x + (size_t)row * 512;
    float s  = xr[u];
    float v0 = xr[128 + u * 3 + 0];
    float v1 = xr[128 + u * 3 + 1];
    float v2 = xr[128 + u * 3 + 2];
    __half* sr = scal + (size_t)row * 384;
    sr[u]       = __float2half(s);
    sr[128 + u] = __float2half(s * s);
    sr[256 + u] = __float2half(v0 * v0 + v1 * v1 + v2 * v2);
}

// ---------------------------------------------------------------------------
// FP16 mma.sync GEMM (fp32 acc), pipelined, ldmatrix fragment loads.
//   C[M, ncols*128] = A[M,K] @ Bp^T, Bp packed [N,K] row-major (K contiguous).
// Block 128x128, BK=32, 3-stage cp.async, 4 warps (2x2 of 64x64 warp tiles).
// smem per stage/tile: 128 rows x 40 halves (pad 8 -> conflict-free LDSM).
// SILU: apply silu in epilogue. OT: __half (GEMM-chain) or float (outputs).
// ---------------------------------------------------------------------------
#define TILE_HALVES 5120            // 128*40
#define STAGE_HALVES 10240          // A tile + B tile

template <bool SILU, typename OT>
__global__ __launch_bounds__(128) void gemm_fp16_kernel(
    const __half* __restrict__ A, int lda, long long bsA,
    const __half* __restrict__ Bp,
    OT* __restrict__ C, int ldc, long long bsC,
    int M, int K)
{
    extern __shared__ __half smh[];
    const uint32_t sb = smem_u32(smh);

    A += (size_t)blockIdx.z * bsA;
    C += (size_t)blockIdx.z * bsC;

    const int tid  = threadIdx.x;
    const int w    = tid >> 5;
    const int lane = tid & 31;
    const int g    = lane >> 2;       // 0..7
    const int tg   = lane & 3;        // 0..3
    const int wm   = (w & 1) * 64;
    const int wn   = (w >> 1) * 64;
    const int rowBase = blockIdx.y * 128;
    const int colBase = blockIdx.x * 128;
    const int T = K >> 5;             // BK=32 steps

    // ldmatrix lane roles: quadrant q -> (row +8 if q&1, k8-half +8 if q>>1).
    const int l8   = lane & 7;
    const int q    = lane >> 3;
    const int rsel = l8 + (q & 1) * 8;       // row within 16-row block
    const int wsel = (q >> 1) * 4;           // word offset for k8-half

    auto load_stage = [&](int s, int kt) {
        const int k0 = kt << 5;
        const uint32_t ab = sb + (uint32_t)(s * STAGE_HALVES) * 2u;
        const uint32_t bb = ab + TILE_HALVES * 2u;
#pragma unroll
        for (int i = 0; i < 4; i++) {
            int flat = i * 128 + tid;        // 0..511
            int r = flat >> 2;               // 0..127
            int c = flat & 3;                // chunk of 8 halves (16B)
            uint32_t so = (uint32_t)(r * 40 + c * 8) * 2u;
            int gr = rowBase + r;
            const __half* srcA = A + (size_t)(gr < M ? gr : 0) * lda + k0 + c * 8;
            cp16(ab + so, srcA, gr < M ? 16 : 0);
            const __half* srcB = Bp + (size_t)(colBase + r) * K + k0 + c * 8;
            cp16(bb + so, srcB, 16);
        }
        asm volatile("cp.async.commit_group;" ::: "memory");
    };

    float acc[4][8][4];
#pragma unroll
    for (int mt = 0; mt < 4; mt++)
#pragma unroll
        for (int nt = 0; nt < 8; nt++)
#pragma unroll
            for (int i = 0; i < 4; i++) acc[mt][nt][i] = 0.0f;

    load_stage(0, 0);
    load_stage(1, 1);

    for (int kt = 0; kt < T; kt++) {
        const int s = kt % 3;
        if (kt + 1 < T) asm volatile("cp.async.wait_group 1;" ::: "memory");
        else            asm volatile("cp.async.wait_group 0;" ::: "memory");
        __syncthreads();
        if (kt + 2 < T) load_stage((kt + 2) % 3, kt + 2);

        const uint32_t a_base = sb + (uint32_t)(s * STAGE_HALVES) * 2u;
        const uint32_t b_base = a_base + TILE_HALVES * 2u;
#pragma unroll
        for (int kf = 0; kf < 2; kf++) {
            const int kw = kf * 8 + wsel;    // word offset within row
            unsigned a[4][4], b[8][2];
#pragma unroll
            for (int mt = 0; mt < 4; mt++) {
                uint32_t addr = a_base + (uint32_t)((wm + mt * 16 + rsel) * 20 + kw) * 4u;
                ldsm_x4(addr, a[mt][0], a[mt][1], a[mt][2], a[mt][3]);
            }
#pragma unroll
            for (int p = 0; p < 4; p++) {
                uint32_t addr = b_base + (uint32_t)((wn + p * 16 + rsel) * 20 + kw) * 4u;
                ldsm_x4(addr, b[2 * p][0], b[2 * p + 1][0], b[2 * p][1], b[2 * p + 1][1]);
            }
#pragma unroll
            for (int mt = 0; mt < 4; mt++)
#pragma unroll
                for (int nt = 0; nt < 8; nt++) {
                    asm volatile(
                        "mma.sync.aligned.m16n8k16.row.col.f32.f16.f16.f32 "
                        "{%0,%1,%2,%3}, {%4,%5,%6,%7}, {%8,%9}, {%0,%1,%2,%3};\n"
                        : "+f"(acc[mt][nt][0]), "+f"(acc[mt][nt][1]),
                          "+f"(acc[mt][nt][2]), "+f"(acc[mt][nt][3])
                        : "r"(a[mt][0]), "r"(a[mt][1]), "r"(a[mt][2]), "r"(a[mt][3]),
                          "r"(b[nt][0]), "r"(b[nt][1]));
                }
        }
        __syncthreads();
    }

    // Epilogue: c0/c1 at (row, 2tg..+1), c2/c3 at (row+8, 2tg..+1).
#pragma unroll
    for (int mt = 0; mt < 4; mt++) {
        int r0 = rowBase + wm + mt * 16 + g;
#pragma unroll
        for (int nt = 0; nt < 8; nt++) {
            int c0 = colBase + wn + nt * 8 + 2 * tg;
            float2 lo = make_float2(acc[mt][nt][0], acc[mt][nt][1]);
            float2 hi = make_float2(acc[mt][nt][2], acc[mt][nt][3]);
            if (SILU) {
                lo.x = silu_f(lo.x); lo.y = silu_f(lo.y);
                hi.x = silu_f(hi.x); hi.y = silu_f(hi.y);
            }
            if (r0 < M) {
                OT* cr = C + (size_t)r0 * ldc + c0;
                if (sizeof(OT) == 2) *reinterpret_cast<__half2*>(cr) = __float22half2_rn(lo);
                else                 *reinterpret_cast<float2*>(cr) = lo;
            }
            if (r0 + 8 < M) {
                OT* cr = C + (size_t)(r0 + 8) * ldc + c0;
                if (sizeof(OT) == 2) *reinterpret_cast<__half2*>(cr) = __float22half2_rn(hi);
                else                 *reinterpret_cast<float2*>(cr) = hi;
            }
        }
    }
}

// ---------------------------------------------------------------------------
// K4: gate scal in place and build gated vec planes (fp16 in/out).
// ---------------------------------------------------------------------------
__global__ void gate_prep_kernel(const float* __restrict__ x, const __half* __restrict__ gates,
                                 __half* __restrict__ scal, __half* __restrict__ vg, int n) {
    int idx = blockIdx.x * blockDim.x + threadIdx.x;
    if (idx >= n * 384) return;
    int row = idx / 384;
    int j = idx - row * 384;
    const __half* g = gates + (size_t)row * 640;
    scal[idx] = __float2half(__half2float(scal[idx]) * __half2float(g[j]));
    if (j < 128) {
        int u = j;
        const float* xr = x + (size_t)row * 512;
        float s  = xr[u];
        float g1 = __half2float(g[384 + u]);
        float c2 = SQ2F * s * __half2float(g[512 + u]);
#pragma unroll
        for (int i = 0; i < 3; i++) {
            float vi = xr[128 + u * 3 + i];
            __half* vgp = vg + ((size_t)i * n + row) * 256;
            vgp[u]       = __float2half(vi * g1);
            vgp[128 + u] = __float2half(vi * c2);
        }
    }
}

// ---------------------------------------------------------------------------
// K7: residuals + scalar layernorm + vector RMS norm, write output [n,512].
// ---------------------------------------------------------------------------
__global__ void finalize_kernel(const float* __restrict__ x, const float* __restrict__ outs,
                                const float* __restrict__ outv, float* __restrict__ out, int n) {
    int gw = (int)((blockIdx.x * blockDim.x + threadIdx.x) >> 5);
    int lane = threadIdx.x & 31;
    if (gw >= n) return;
    const float* xr = x + (size_t)gw * 512;
    float* orow = out + (size_t)gw * 512;

    float so[4];
    float sum = 0.f;
#pragma unroll
    for (int t = 0; t < 4; t++) {
        int u = lane + 32 * t;
        so[t] = outs[(size_t)gw * 128 + u] + xr[u];
        sum += so[t];
    }
#pragma unroll
    for (int o = 16; o > 0; o >>= 1) sum += __shfl_xor_sync(0xffffffffu, sum, o);
    float mean = sum * (1.0f / 128.0f);
    float ssum = 0.f;
#pragma unroll
    for (int t = 0; t < 4; t++) {
        so[t] -= mean;
        ssum += so[t] * so[t];
    }
#pragma unroll
    for (int o = 16; o > 0; o >>= 1) ssum += __shfl_xor_sync(0xffffffffu, ssum, o);
    float inv = 1.0f / (sqrtf(ssum * (1.0f / 128.0f)) + 1e-6f);
#pragma unroll
    for (int t = 0; t < 4; t++) orow[lane + 32 * t] = so[t] * inv;

    float vo[4][3];
    float vs = 0.f;
#pragma unroll
    for (int t = 0; t < 4; t++) {
        int u = lane + 32 * t;
#pragma unroll
        for (int i = 0; i < 3; i++) {
            vo[t][i] = outv[((size_t)i * n + gw) * 128 + u] + xr[128 + u * 3 + i];
            vs += vo[t][i] * vo[t][i];
        }
    }
#pragma unroll
    for (int o = 16; o > 0; o >>= 1) vs += __shfl_xor_sync(0xffffffffu, vs, o);
    float vinv = 1.0f / (sqrtf(vs * (1.0f / 128.0f)) + 1e-6f);
#pragma unroll
    for (int t = 0; t < 4; t++) {
        int u = lane + 32 * t;
#pragma unroll
        for (int i = 0; i < 3; i++)
            orow[128 + u * 3 + i] = vo[t][i] * vinv;
    }
}

// ---------------------------------------------------------------------------
extern "C" void kernel_launch(void* const* d_in, const int* in_sizes, int n_in,
                              void* d_out, int out_size) {
    const float* x  = (const float*)d_in[0];
    const float* W1 = (const float*)d_in[1];   // [384,384]
    const float* W2 = (const float*)d_in[2];   // [384,768] (cols 640:768 dead)
    const float* Ws = (const float*)d_in[3];   // [384,128]
    const float* Wv = (const float*)d_in[4];   // [256,128]
    float* out = (float*)d_out;
    int n = in_sizes[0] / 512;

    __half *scal, *h, *gates, *vg, *w1p, *w2p, *wsp, *wvp;
    float *outs, *outv;
    cudaGetSymbolAddress((void**)&scal,  g_scal);
    cudaGetSymbolAddress((void**)&h,     g_h);
    cudaGetSymbolAddress((void**)&gates, g_gates);
    cudaGetSymbolAddress((void**)&vg,    g_vg);
    cudaGetSymbolAddress((void**)&outs,  g_outs);
    cudaGetSymbolAddress((void**)&outv,  g_outv);
    cudaGetSymbolAddress((void**)&w1p,   g_w1p);
    cudaGetSymbolAddress((void**)&w2p,   g_w2p);
    cudaGetSymbolAddress((void**)&wsp,   g_wsp);
    cudaGetSymbolAddress((void**)&wvp,   g_wvp);

    const int SMEM_BYTES = 3 * STAGE_HALVES * 2;   // 61440
    cudaFuncSetAttribute((const void*)gemm_fp16_kernel<true, __half>,
                         cudaFuncAttributeMaxDynamicSharedMemorySize, SMEM_BYTES);
    cudaFuncSetAttribute((const void*)gemm_fp16_kernel<false, float>,
                         cudaFuncAttributeMaxDynamicSharedMemorySize, SMEM_BYTES);

    int mblocks = (n + 127) / 128;

    // Pack weights -> [N,K] K-major fp16.
    pack_w_kernel<<<(384 * 384 + 255) / 256, 256>>>(W1, w1p, 384, 384, 384);
    pack_w_kernel<<<(640 * 384 + 255) / 256, 256>>>(W2, w2p, 384, 640, 768);
    pack_w_kernel<<<(128 * 384 + 255) / 256, 256>>>(Ws, wsp, 384, 128, 128);
    pack_w_kernel<<<(128 * 256 + 255) / 256, 256>>>(Wv, wvp, 256, 128, 128);

    // K1: scal features (fp16)
    prep_scal_kernel<<<(n * 128 + 255) / 256, 256>>>(x, scal, n);

    // G1: h = silu(scal @ W1) -> fp16
    dim3 g1(3, mblocks, 1);
    gemm_fp16_kernel<true, __half><<<g1, 128, SMEM_BYTES>>>(
        scal, 384, 0LL, w1p, h, 384, 0LL, n, 384);

    // G2: gates = silu(h @ W2[:, :640]) -> fp16
    dim3 g2(5, mblocks, 1);
    gemm_fp16_kernel<true, __half><<<g2, 128, SMEM_BYTES>>>(
        h, 384, 0LL, w2p, gates, 640, 0LL, n, 384);

    // K4: gate scal in-place, build vg planes
    gate_prep_kernel<<<(n * 384 + 255) / 256, 256>>>(x, gates, scal, vg, n);

    // G5: outs = scal_gated @ Ws -> fp32
    dim3 g5(1, mblocks, 1);
    gemm_fp16_kernel<false, float><<<g5, 128, SMEM_BYTES>>>(
        scal, 384, 0LL, wsp, outs, 128, 0LL, n, 384);

    // G6: outv_i = vg_i @ Wv (3 planes over z) -> fp32
    dim3 g6(1, mblocks, 3);
    gemm_fp16_kernel<false, float><<<g6, 128, SMEM_BYTES>>>(
        vg, 256, (long long)n * 256, wvp, outv, 128, (long long)n * 128, n, 256);

    // K7: residual + norms + output
    finalize_kernel<<<(n + 7) / 8, 256>>>(x, outs, outv, out, n);
}